// round 4
// baseline (speedup 1.0000x reference)
#include <cuda_runtime.h>

#define NN 50000
#define NE 1600000
#define HH 64
#define NG 16
#define DOUT 2

#define SCAN_B 512
#define NB_SCAN ((NN + SCAN_B - 1) / SCAN_B)   // 98

// Scratch (device globals; no allocation allowed)
__device__ __align__(16) float g_relu_sum[NN * HH];  // sum of relu(h1) per dest node
__device__ __align__(16) float g_agg[NN * HH];       // after ew2 + deg*eb2
__device__ __align__(16) float g_t[NN * HH];         // node hidden
__device__ __align__(16) float g_pooled[NG * HH];
__device__ int g_count[NN];
__device__ int g_off[NN];
__device__ int g_cur[NN];
__device__ int g_bsum[NB_SCAN];
__device__ int g_boff[NB_SCAN];
__device__ int g_eidx[NE];

// ---------------------------------------------------------------------------
__global__ void zero_kernel() {
    int i = blockIdx.x * blockDim.x + threadIdx.x;
    if (i < NN) g_count[i] = 0;
    if (i < NG * HH) g_pooled[i] = 0.f;
}

// ---------------------------------------------------------------------------
__global__ void __launch_bounds__(256) hist_kernel(const int* __restrict__ ei) {
    int e = blockIdx.x * 256 + threadIdx.x;
    if (e >= NE) return;
    int c = ei[NE + e];                 // int32 indices (JAX x64 disabled)
    atomicAdd(&g_count[c], 1);
}

// ---------------------------------------------------------------------------
// Scan stage 1: per-block exclusive scan of counts, emit block totals.
__global__ void __launch_bounds__(SCAN_B) scan_block_kernel() {
    __shared__ int sd[SCAN_B];
    int t = threadIdx.x;
    int i = blockIdx.x * SCAN_B + t;
    int v = (i < NN) ? g_count[i] : 0;
    sd[t] = v;
    __syncthreads();
    for (int d = 1; d < SCAN_B; d <<= 1) {
        int u = (t >= d) ? sd[t - d] : 0;
        __syncthreads();
        sd[t] += u;
        __syncthreads();
    }
    if (i < NN) g_off[i] = sd[t] - v;          // exclusive within block
    if (t == SCAN_B - 1) g_bsum[blockIdx.x] = sd[t];
}

// Scan stage 2: exclusive scan of 98 block totals (single block).
__global__ void __launch_bounds__(128) scan_top_kernel() {
    __shared__ int sd[128];
    int t = threadIdx.x;
    int v = (t < NB_SCAN) ? g_bsum[t] : 0;
    sd[t] = v;
    __syncthreads();
    for (int d = 1; d < 128; d <<= 1) {
        int u = (t >= d) ? sd[t - d] : 0;
        __syncthreads();
        sd[t] += u;
        __syncthreads();
    }
    if (t < NB_SCAN) g_boff[t] = sd[t] - v;
}

// Scan stage 3: add block offsets, init cursors.
__global__ void __launch_bounds__(256) scan_add_kernel() {
    int i = blockIdx.x * 256 + threadIdx.x;
    if (i >= NN) return;
    int o = g_off[i] + g_boff[i / SCAN_B];
    g_off[i] = o;
    g_cur[i] = o;
}

// ---------------------------------------------------------------------------
// Fill CSR buckets: edge ids grouped by destination node.
__global__ void __launch_bounds__(256) fill_kernel(const int* __restrict__ ei) {
    int e = blockIdx.x * 256 + threadIdx.x;
    if (e >= NE) return;
    int c = ei[NE + e];
    int p = atomicAdd(&g_cur[c], 1);
    g_eidx[p] = e;
}

// ---------------------------------------------------------------------------
// Gather kernel: warp per node. Accumulate sum over in-edges of
// relu(eb1 + x[r]*ew1[0] + x[c]*ew1[1] + ea@ew1[2:5]) into registers.
// Lane l owns features l and l+32. No float atomics.
__global__ void __launch_bounds__(256) gather_kernel(
    const float* __restrict__ x,
    const int* __restrict__ ei,
    const float* __restrict__ ea,
    const float* __restrict__ ew1,   // [5,64]
    const float* __restrict__ eb1)   // [64]
{
    int warp = threadIdx.x >> 5, lane = threadIdx.x & 31;
    int n = blockIdx.x * 8 + warp;
    if (n >= NN) return;

    int start = g_off[n];
    int cnt   = g_count[n];
    float xc  = __ldg(&x[n]);

    // Per-lane weight columns for features lane and lane+32
    int ja = lane, jb = lane + 32;
    float w0a = __ldg(&ew1[0 * 64 + ja]), w1a = __ldg(&ew1[1 * 64 + ja]);
    float w2a = __ldg(&ew1[2 * 64 + ja]), w3a = __ldg(&ew1[3 * 64 + ja]);
    float w4a = __ldg(&ew1[4 * 64 + ja]), ba  = __ldg(&eb1[ja]);
    float w0b = __ldg(&ew1[0 * 64 + jb]), w1b = __ldg(&ew1[1 * 64 + jb]);
    float w2b = __ldg(&ew1[2 * 64 + jb]), w3b = __ldg(&ew1[3 * 64 + jb]);
    float w4b = __ldg(&ew1[4 * 64 + jb]), bb  = __ldg(&eb1[jb]);

    // fold xc into bias once: bias' = b + xc*w1
    float ca = fmaf(xc, w1a, ba);
    float cb = fmaf(xc, w1b, bb);

    float acc0 = 0.f, acc1 = 0.f;

    for (int g0 = 0; g0 < cnt; g0 += 32) {
        int idx = g0 + lane;
        float xr = 0.f, a0 = 0.f, a1 = 0.f, a2 = 0.f;
        if (idx < cnt) {
            int e = g_eidx[start + idx];
            int r = __ldg(&ei[e]);
            xr = __ldg(&x[r]);
            a0 = __ldg(&ea[3 * e + 0]);
            a1 = __ldg(&ea[3 * e + 1]);
            a2 = __ldg(&ea[3 * e + 2]);
        }
        int m = min(32, cnt - g0);
        for (int k = 0; k < m; k++) {
            float sxr = __shfl_sync(0xffffffffu, xr, k);
            float s0  = __shfl_sync(0xffffffffu, a0, k);
            float s1  = __shfl_sync(0xffffffffu, a1, k);
            float s2  = __shfl_sync(0xffffffffu, a2, k);
            float h0 = fmaf(sxr, w0a, fmaf(s0, w2a, fmaf(s1, w3a, fmaf(s2, w4a, ca))));
            float h1 = fmaf(sxr, w0b, fmaf(s0, w2b, fmaf(s1, w3b, fmaf(s2, w4b, cb))));
            acc0 += fmaxf(h0, 0.f);
            acc1 += fmaxf(h1, 0.f);
        }
    }
    g_relu_sum[(size_t)n * HH + ja] = acc0;
    g_relu_sum[(size_t)n * HH + jb] = acc1;
}

// ---------------------------------------------------------------------------
// 4x4 FMA micro-tile: a[0..3] += iv dot 4 consecutive weight rows (row stride 64)
__device__ __forceinline__ void fma4x4(float4& a, float4 iv, const float* wr) {
    float4 w0 = *(const float4*)(wr);
    float4 w1 = *(const float4*)(wr + 64);
    float4 w2 = *(const float4*)(wr + 128);
    float4 w3 = *(const float4*)(wr + 192);
    a.x = fmaf(iv.x, w0.x, a.x); a.y = fmaf(iv.x, w0.y, a.y);
    a.z = fmaf(iv.x, w0.z, a.z); a.w = fmaf(iv.x, w0.w, a.w);
    a.x = fmaf(iv.y, w1.x, a.x); a.y = fmaf(iv.y, w1.y, a.y);
    a.z = fmaf(iv.y, w1.z, a.z); a.w = fmaf(iv.y, w1.w, a.w);
    a.x = fmaf(iv.z, w2.x, a.x); a.y = fmaf(iv.z, w2.y, a.y);
    a.z = fmaf(iv.z, w2.z, a.z); a.w = fmaf(iv.z, w2.w, a.w);
    a.x = fmaf(iv.w, w3.x, a.x); a.y = fmaf(iv.w, w3.y, a.y);
    a.z = fmaf(iv.w, w3.z, a.z); a.w = fmaf(iv.w, w3.w, a.w);
}

// ---------------------------------------------------------------------------
// B1: g_agg = deg * eb2 + g_relu_sum @ ew2
__global__ void __launch_bounds__(256) node_agg_kernel(
    const float* __restrict__ ew2, const float* __restrict__ eb2)
{
    __shared__ __align__(16) float sw[64 * 64];
    __shared__ float sb[64];
    for (int i = threadIdx.x; i < 4096; i += 256) sw[i] = ew2[i];
    if (threadIdx.x < 64) sb[threadIdx.x] = eb2[threadIdx.x];
    __syncthreads();

    int n = blockIdx.x * 256 + threadIdx.x;
    if (n >= NN) return;

    float dg = (float)g_count[n];
    const float4* in = (const float4*)&g_relu_sum[(size_t)n * HH];
    float4* outp = (float4*)&g_agg[(size_t)n * HH];
#pragma unroll 2
    for (int jv = 0; jv < 16; jv++) {
        float4 a;
        a.x = dg * sb[jv * 4 + 0]; a.y = dg * sb[jv * 4 + 1];
        a.z = dg * sb[jv * 4 + 2]; a.w = dg * sb[jv * 4 + 3];
#pragma unroll 4
        for (int kv = 0; kv < 16; kv++) {
            float4 iv = __ldg(&in[kv]);
            fma4x4(a, iv, &sw[kv * 4 * 64 + jv * 4]);
        }
        outp[jv] = a;
    }
}

// ---------------------------------------------------------------------------
// B2: g_t = relu(nb1 + x*nw1[0] + g_agg @ nw1[1:])
__global__ void __launch_bounds__(256) node_hidden_kernel(
    const float* __restrict__ x,
    const float* __restrict__ nw1,   // [65,64]
    const float* __restrict__ nb1)
{
    __shared__ __align__(16) float sw[65 * 64];
    __shared__ float sb[64];
    for (int i = threadIdx.x; i < 65 * 64; i += 256) sw[i] = nw1[i];
    if (threadIdx.x < 64) sb[threadIdx.x] = nb1[threadIdx.x];
    __syncthreads();

    int n = blockIdx.x * 256 + threadIdx.x;
    if (n >= NN) return;

    float xn = __ldg(&x[n]);
    const float4* in = (const float4*)&g_agg[(size_t)n * HH];
    float4* outp = (float4*)&g_t[(size_t)n * HH];
#pragma unroll 2
    for (int jv = 0; jv < 16; jv++) {
        float4 a;
        a.x = fmaf(xn, sw[jv * 4 + 0], sb[jv * 4 + 0]);
        a.y = fmaf(xn, sw[jv * 4 + 1], sb[jv * 4 + 1]);
        a.z = fmaf(xn, sw[jv * 4 + 2], sb[jv * 4 + 2]);
        a.w = fmaf(xn, sw[jv * 4 + 3], sb[jv * 4 + 3]);
#pragma unroll 4
        for (int kv = 0; kv < 16; kv++) {
            float4 iv = __ldg(&in[kv]);
            fma4x4(a, iv, &sw[(1 + kv * 4) * 64 + jv * 4]);
        }
        a.x = fmaxf(a.x, 0.f); a.y = fmaxf(a.y, 0.f);
        a.z = fmaxf(a.z, 0.f); a.w = fmaxf(a.w, 0.f);
        outp[jv] = a;
    }
}

// ---------------------------------------------------------------------------
// B3: h = nb2 + g_t @ nw2; pooled[batch[n]] += h  (smem pool -> global scalar RED)
__global__ void __launch_bounds__(256) node_out_kernel(
    const int* __restrict__ batch,
    const float* __restrict__ nw2,
    const float* __restrict__ nb2)
{
    __shared__ __align__(16) float sw[64 * 64];
    __shared__ float sb[64];
    __shared__ float spool[NG * HH];
    for (int i = threadIdx.x; i < 4096; i += 256) sw[i] = nw2[i];
    if (threadIdx.x < 64) sb[threadIdx.x] = nb2[threadIdx.x];
    for (int i = threadIdx.x; i < NG * HH; i += 256) spool[i] = 0.f;
    __syncthreads();

    int n = blockIdx.x * 256 + threadIdx.x;
    bool act = (n < NN);
    int g = 0;
    if (act) g = batch[n];

    if (act) {
        const float4* in = (const float4*)&g_t[(size_t)n * HH];
#pragma unroll 2
        for (int jv = 0; jv < 16; jv++) {
            float4 a;
            a.x = sb[jv * 4 + 0]; a.y = sb[jv * 4 + 1];
            a.z = sb[jv * 4 + 2]; a.w = sb[jv * 4 + 3];
#pragma unroll 4
            for (int kv = 0; kv < 16; kv++) {
                float4 iv = __ldg(&in[kv]);
                fma4x4(a, iv, &sw[kv * 4 * 64 + jv * 4]);
            }
            atomicAdd(&spool[g * HH + jv * 4 + 0], a.x);
            atomicAdd(&spool[g * HH + jv * 4 + 1], a.y);
            atomicAdd(&spool[g * HH + jv * 4 + 2], a.z);
            atomicAdd(&spool[g * HH + jv * 4 + 3], a.w);
        }
    }
    __syncthreads();
    for (int i = threadIdx.x; i < NG * HH; i += 256)
        atomicAdd(&g_pooled[i], spool[i]);
}

// ---------------------------------------------------------------------------
// Head MLP: 3x (64->64 relu) + 64->2. One block of 1024 threads: (g, j).
__global__ void __launch_bounds__(1024) out_kernel(
    const float* __restrict__ ow1, const float* __restrict__ ob1,
    const float* __restrict__ ow2, const float* __restrict__ ob2,
    const float* __restrict__ ow3, const float* __restrict__ ob3,
    const float* __restrict__ ow4, const float* __restrict__ ob4,
    float* __restrict__ out)
{
    __shared__ float sa[NG * HH];
    __shared__ float sbuf[NG * HH];
    int tid = threadIdx.x;
    sa[tid] = g_pooled[tid];
    __syncthreads();

    int g = tid >> 6, j = tid & 63;

    float v = __ldg(&ob1[j]);
#pragma unroll 16
    for (int k = 0; k < 64; k++) v = fmaf(sa[g * 64 + k], __ldg(&ow1[k * 64 + j]), v);
    sbuf[tid] = fmaxf(v, 0.f);
    __syncthreads();

    v = __ldg(&ob2[j]);
#pragma unroll 16
    for (int k = 0; k < 64; k++) v = fmaf(sbuf[g * 64 + k], __ldg(&ow2[k * 64 + j]), v);
    sa[tid] = fmaxf(v, 0.f);
    __syncthreads();

    v = __ldg(&ob3[j]);
#pragma unroll 16
    for (int k = 0; k < 64; k++) v = fmaf(sa[g * 64 + k], __ldg(&ow3[k * 64 + j]), v);
    sbuf[tid] = fmaxf(v, 0.f);
    __syncthreads();

    if (j < DOUT) {
        float o = __ldg(&ob4[j]);
#pragma unroll 16
        for (int k = 0; k < 64; k++)
            o = fmaf(sbuf[g * 64 + k], __ldg(&ow4[k * DOUT + j]), o);
        out[g * DOUT + j] = o;
    }
}

// ---------------------------------------------------------------------------
extern "C" void kernel_launch(void* const* d_in, const int* in_sizes, int n_in,
                              void* d_out, int out_size) {
    const float* x     = (const float*)d_in[0];
    const int* ei      = (const int*)d_in[1];     // int32 (JAX x64 disabled)
    const float* ea    = (const float*)d_in[2];
    const int* batch   = (const int*)d_in[3];     // int32
    const float* ew1 = (const float*)d_in[4];
    const float* eb1 = (const float*)d_in[5];
    const float* ew2 = (const float*)d_in[6];
    const float* eb2 = (const float*)d_in[7];
    const float* nw1 = (const float*)d_in[8];
    const float* nb1 = (const float*)d_in[9];
    const float* nw2 = (const float*)d_in[10];
    const float* nb2 = (const float*)d_in[11];
    const float* ow1 = (const float*)d_in[12];
    const float* ob1 = (const float*)d_in[13];
    const float* ow2 = (const float*)d_in[14];
    const float* ob2 = (const float*)d_in[15];
    const float* ow3 = (const float*)d_in[16];
    const float* ob3 = (const float*)d_in[17];
    const float* ow4 = (const float*)d_in[18];
    const float* ob4 = (const float*)d_in[19];
    float* out = (float*)d_out;

    zero_kernel<<<(NN + 255) / 256, 256>>>();
    hist_kernel<<<(NE + 255) / 256, 256>>>(ei);
    scan_block_kernel<<<NB_SCAN, SCAN_B>>>();
    scan_top_kernel<<<1, 128>>>();
    scan_add_kernel<<<(NN + 255) / 256, 256>>>();
    fill_kernel<<<(NE + 255) / 256, 256>>>(ei);

    gather_kernel<<<(NN + 7) / 8, 256>>>(x, ei, ea, ew1, eb1);

    int nblocks = (NN + 255) / 256;
    node_agg_kernel<<<nblocks, 256>>>(ew2, eb2);
    node_hidden_kernel<<<nblocks, 256>>>(x, nw1, nb1);
    node_out_kernel<<<nblocks, 256>>>(batch, nw2, nb2);

    out_kernel<<<1, NG * HH>>>(ow1, ob1, ow2, ob2, ow3, ob3, ow4, ob4, out);
}

// round 5
// speedup vs baseline: 1.3421x; 1.3421x over previous
#include <cuda_runtime.h>

#define NN 50000
#define NE 1600000
#define HH 64
#define NG 16
#define DOUT 2

// Scratch (device globals; no allocation allowed)
__device__ __align__(16) float g_relu_sum[NN * HH];  // sum of relu(h1) per dest node
__device__ __align__(16) float g_pooled[NG * HH];
__device__ int g_count[NN];
__device__ int g_off[NN];
__device__ int g_cur[NN];
__device__ int g_eidx[NE];

// ---------------------------------------------------------------------------
__global__ void zero_counts_kernel() {
    int i = blockIdx.x * blockDim.x + threadIdx.x;
    if (i < NN) g_count[i] = 0;
}

__global__ void __launch_bounds__(1024) zero_pooled_kernel() {
    g_pooled[threadIdx.x] = 0.f;   // exactly NG*HH = 1024
}

// ---------------------------------------------------------------------------
__global__ void __launch_bounds__(256) hist_kernel(const int* __restrict__ ei) {
    int e = blockIdx.x * 256 + threadIdx.x;
    if (e >= NE) return;
    atomicAdd(&g_count[ei[NE + e]], 1);
}

// ---------------------------------------------------------------------------
// Single-block exclusive scan of g_count -> g_off, g_cur. 1024 threads,
// 49 items per thread (serial) + Hillis-Steele over the 1024 partials.
#define SCAN_T 1024
#define SCAN_ITEMS 49   // 1024*49 = 50176 >= 50000
__global__ void __launch_bounds__(SCAN_T) scan_kernel() {
    __shared__ int sd[SCAN_T];
    int t = threadIdx.x;
    int base = t * SCAN_ITEMS;

    int loc[SCAN_ITEMS];
    int sum = 0;
#pragma unroll
    for (int i = 0; i < SCAN_ITEMS; i++) {
        int idx = base + i;
        int v = (idx < NN) ? g_count[idx] : 0;
        loc[i] = sum;          // exclusive prefix within thread
        sum += v;
    }
    sd[t] = sum;
    __syncthreads();
#pragma unroll
    for (int d = 1; d < SCAN_T; d <<= 1) {
        int u = (t >= d) ? sd[t - d] : 0;
        __syncthreads();
        sd[t] += u;
        __syncthreads();
    }
    int tbase = sd[t] - sum;   // exclusive prefix of this thread's chunk
#pragma unroll
    for (int i = 0; i < SCAN_ITEMS; i++) {
        int idx = base + i;
        if (idx < NN) {
            int o = tbase + loc[i];
            g_off[idx] = o;
            g_cur[idx] = o;
        }
    }
}

// ---------------------------------------------------------------------------
// Fill CSR buckets: edge ids grouped by destination node.
__global__ void __launch_bounds__(256) fill_kernel(const int* __restrict__ ei) {
    int e = blockIdx.x * 256 + threadIdx.x;
    if (e >= NE) return;
    int c = ei[NE + e];
    int p = atomicAdd(&g_cur[c], 1);
    g_eidx[p] = e;
}

// ---------------------------------------------------------------------------
// Gather kernel: warp per node. Lanes batch-load 32 edges' scalars into a
// smem float4 stage; inner loop does ONE broadcast LDS.128 per edge.
// Lane l owns output features l and l+32. No float atomics.
__global__ void __launch_bounds__(256) gather_kernel(
    const float* __restrict__ x,
    const int* __restrict__ ei,
    const float* __restrict__ ea,
    const float* __restrict__ ew1,   // [5,64]
    const float* __restrict__ eb1)   // [64]
{
    __shared__ __align__(16) float4 stage[8][32];
    int warp = threadIdx.x >> 5, lane = threadIdx.x & 31;
    int n = blockIdx.x * 8 + warp;
    if (n >= NN) return;

    int start = g_off[n];
    int cnt   = g_count[n];
    float xc  = __ldg(&x[n]);

    int ja = lane, jb = lane + 32;
    float w0a = __ldg(&ew1[0 * 64 + ja]), w1a = __ldg(&ew1[1 * 64 + ja]);
    float w2a = __ldg(&ew1[2 * 64 + ja]), w3a = __ldg(&ew1[3 * 64 + ja]);
    float w4a = __ldg(&ew1[4 * 64 + ja]), ba  = __ldg(&eb1[ja]);
    float w0b = __ldg(&ew1[0 * 64 + jb]), w1b = __ldg(&ew1[1 * 64 + jb]);
    float w2b = __ldg(&ew1[2 * 64 + jb]), w3b = __ldg(&ew1[3 * 64 + jb]);
    float w4b = __ldg(&ew1[4 * 64 + jb]), bb  = __ldg(&eb1[jb]);

    // fold xc into bias once: bias' = b + xc*w1
    float ca = fmaf(xc, w1a, ba);
    float cb = fmaf(xc, w1b, bb);

    float acc0 = 0.f, acc1 = 0.f;

    for (int g0 = 0; g0 < cnt; g0 += 32) {
        int idx = g0 + lane;
        float4 d = make_float4(0.f, 0.f, 0.f, 0.f);
        if (idx < cnt) {
            int e = g_eidx[start + idx];
            int r = __ldg(&ei[e]);
            d.x = __ldg(&x[r]);
            d.y = __ldg(&ea[3 * e + 0]);
            d.z = __ldg(&ea[3 * e + 1]);
            d.w = __ldg(&ea[3 * e + 2]);
        }
        stage[warp][lane] = d;
        __syncwarp();
        int m = min(32, cnt - g0);
#pragma unroll 4
        for (int k = 0; k < m; k++) {
            float4 s = stage[warp][k];   // broadcast LDS.128
            float h0 = fmaf(s.x, w0a, fmaf(s.y, w2a, fmaf(s.z, w3a, fmaf(s.w, w4a, ca))));
            float h1 = fmaf(s.x, w0b, fmaf(s.y, w2b, fmaf(s.z, w3b, fmaf(s.w, w4b, cb))));
            acc0 += fmaxf(h0, 0.f);
            acc1 += fmaxf(h1, 0.f);
        }
        __syncwarp();
    }
    g_relu_sum[(size_t)n * HH + ja] = acc0;
    g_relu_sum[(size_t)n * HH + jb] = acc1;
}

// ---------------------------------------------------------------------------
// 4x4 FMA micro-tile: a[0..3] += iv dot 4 consecutive weight rows (row stride 64)
__device__ __forceinline__ void fma4x4(float4& a, float4 iv, const float* wr) {
    float4 w0 = *(const float4*)(wr);
    float4 w1 = *(const float4*)(wr + 64);
    float4 w2 = *(const float4*)(wr + 128);
    float4 w3 = *(const float4*)(wr + 192);
    a.x = fmaf(iv.x, w0.x, a.x); a.y = fmaf(iv.x, w0.y, a.y);
    a.z = fmaf(iv.x, w0.z, a.z); a.w = fmaf(iv.x, w0.w, a.w);
    a.x = fmaf(iv.y, w1.x, a.x); a.y = fmaf(iv.y, w1.y, a.y);
    a.z = fmaf(iv.y, w1.z, a.z); a.w = fmaf(iv.y, w1.w, a.w);
    a.x = fmaf(iv.z, w2.x, a.x); a.y = fmaf(iv.z, w2.y, a.y);
    a.z = fmaf(iv.z, w2.z, a.z); a.w = fmaf(iv.z, w2.w, a.w);
    a.x = fmaf(iv.w, w3.x, a.x); a.y = fmaf(iv.w, w3.y, a.y);
    a.z = fmaf(iv.w, w3.z, a.z); a.w = fmaf(iv.w, w3.w, a.w);
}

// ---------------------------------------------------------------------------
// Fused node pipeline: 64-float vector lives in registers across 3 GEMV
// stages; weights phase-swapped through one smem buffer. Ends with pooling.
__global__ void __launch_bounds__(128) node_fused_kernel(
    const float* __restrict__ x,
    const int* __restrict__ batch,
    const float* __restrict__ ew2, const float* __restrict__ eb2,
    const float* __restrict__ nw1, const float* __restrict__ nb1,
    const float* __restrict__ nw2, const float* __restrict__ nb2)
{
    __shared__ __align__(16) float sw[65 * 64];
    __shared__ float sb[64];
    __shared__ float spool[NG * HH];

    int tid = threadIdx.x;
    int n = blockIdx.x * 128 + tid;
    bool act = (n < NN);

    for (int i = tid; i < NG * HH; i += 128) spool[i] = 0.f;

    // ---- Phase A: agg = deg*eb2 + relu_sum @ ew2 ----
    for (int i = tid; i < 4096; i += 128) sw[i] = ew2[i];
    if (tid < 64) sb[tid] = eb2[tid];
    __syncthreads();

    float4 v[16], o[16];
    float dg = 0.f, xn = 0.f;
    int g = 0;
    if (act) {
        dg = (float)g_count[n];
        xn = __ldg(&x[n]);
        g  = batch[n];
        const float4* in = (const float4*)&g_relu_sum[(size_t)n * HH];
#pragma unroll
        for (int kv = 0; kv < 16; kv++) v[kv] = __ldg(&in[kv]);
#pragma unroll 2
        for (int jv = 0; jv < 16; jv++) {
            float4 a;
            a.x = dg * sb[jv * 4 + 0]; a.y = dg * sb[jv * 4 + 1];
            a.z = dg * sb[jv * 4 + 2]; a.w = dg * sb[jv * 4 + 3];
#pragma unroll 4
            for (int kv = 0; kv < 16; kv++)
                fma4x4(a, v[kv], &sw[kv * 4 * 64 + jv * 4]);
            o[jv] = a;
        }
    }
    __syncthreads();

    // ---- Phase B: t = relu(nb1 + x*nw1[0] + agg @ nw1[1:]) ----
    for (int i = tid; i < 65 * 64; i += 128) sw[i] = nw1[i];
    if (tid < 64) sb[tid] = nb1[tid];
    __syncthreads();

    if (act) {
#pragma unroll 2
        for (int jv = 0; jv < 16; jv++) {
            float4 a;
            a.x = fmaf(xn, sw[jv * 4 + 0], sb[jv * 4 + 0]);
            a.y = fmaf(xn, sw[jv * 4 + 1], sb[jv * 4 + 1]);
            a.z = fmaf(xn, sw[jv * 4 + 2], sb[jv * 4 + 2]);
            a.w = fmaf(xn, sw[jv * 4 + 3], sb[jv * 4 + 3]);
#pragma unroll 4
            for (int kv = 0; kv < 16; kv++)
                fma4x4(a, o[kv], &sw[(1 + kv * 4) * 64 + jv * 4]);
            a.x = fmaxf(a.x, 0.f); a.y = fmaxf(a.y, 0.f);
            a.z = fmaxf(a.z, 0.f); a.w = fmaxf(a.w, 0.f);
            v[jv] = a;
        }
    }
    __syncthreads();

    // ---- Phase C: h = nb2 + t @ nw2; pool into spool ----
    for (int i = tid; i < 4096; i += 128) sw[i] = nw2[i];
    if (tid < 64) sb[tid] = nb2[tid];
    __syncthreads();

    if (act) {
#pragma unroll 2
        for (int jv = 0; jv < 16; jv++) {
            float4 a;
            a.x = sb[jv * 4 + 0]; a.y = sb[jv * 4 + 1];
            a.z = sb[jv * 4 + 2]; a.w = sb[jv * 4 + 3];
#pragma unroll 4
            for (int kv = 0; kv < 16; kv++)
                fma4x4(a, v[kv], &sw[kv * 4 * 64 + jv * 4]);
            // warp-uniform addresses (same jv, mostly same g) -> REDUX-aggregated
            atomicAdd(&spool[g * HH + jv * 4 + 0], a.x);
            atomicAdd(&spool[g * HH + jv * 4 + 1], a.y);
            atomicAdd(&spool[g * HH + jv * 4 + 2], a.z);
            atomicAdd(&spool[g * HH + jv * 4 + 3], a.w);
        }
    }
    __syncthreads();
    for (int i = tid; i < NG * HH; i += 128)
        atomicAdd(&g_pooled[i], spool[i]);
}

// ---------------------------------------------------------------------------
// Head MLP: 3x (64->64 relu) + 64->2. One block of 1024 threads: (g, j).
__global__ void __launch_bounds__(1024) out_kernel(
    const float* __restrict__ ow1, const float* __restrict__ ob1,
    const float* __restrict__ ow2, const float* __restrict__ ob2,
    const float* __restrict__ ow3, const float* __restrict__ ob3,
    const float* __restrict__ ow4, const float* __restrict__ ob4,
    float* __restrict__ out)
{
    __shared__ float sa[NG * HH];
    __shared__ float sbuf[NG * HH];
    int tid = threadIdx.x;
    sa[tid] = g_pooled[tid];
    __syncthreads();

    int g = tid >> 6, j = tid & 63;

    float v = __ldg(&ob1[j]);
#pragma unroll 16
    for (int k = 0; k < 64; k++) v = fmaf(sa[g * 64 + k], __ldg(&ow1[k * 64 + j]), v);
    sbuf[tid] = fmaxf(v, 0.f);
    __syncthreads();

    v = __ldg(&ob2[j]);
#pragma unroll 16
    for (int k = 0; k < 64; k++) v = fmaf(sbuf[g * 64 + k], __ldg(&ow2[k * 64 + j]), v);
    sa[tid] = fmaxf(v, 0.f);
    __syncthreads();

    v = __ldg(&ob3[j]);
#pragma unroll 16
    for (int k = 0; k < 64; k++) v = fmaf(sa[g * 64 + k], __ldg(&ow3[k * 64 + j]), v);
    sbuf[tid] = fmaxf(v, 0.f);
    __syncthreads();

    if (j < DOUT) {
        float o = __ldg(&ob4[j]);
#pragma unroll 16
        for (int k = 0; k < 64; k++)
            o = fmaf(sbuf[g * 64 + k], __ldg(&ow4[k * DOUT + j]), o);
        out[g * DOUT + j] = o;
    }
}

// ---------------------------------------------------------------------------
extern "C" void kernel_launch(void* const* d_in, const int* in_sizes, int n_in,
                              void* d_out, int out_size) {
    const float* x     = (const float*)d_in[0];
    const int* ei      = (const int*)d_in[1];     // int32 (JAX x64 disabled)
    const float* ea    = (const float*)d_in[2];
    const int* batch   = (const int*)d_in[3];     // int32
    const float* ew1 = (const float*)d_in[4];
    const float* eb1 = (const float*)d_in[5];
    const float* ew2 = (const float*)d_in[6];
    const float* eb2 = (const float*)d_in[7];
    const float* nw1 = (const float*)d_in[8];
    const float* nb1 = (const float*)d_in[9];
    const float* nw2 = (const float*)d_in[10];
    const float* nb2 = (const float*)d_in[11];
    const float* ow1 = (const float*)d_in[12];
    const float* ob1 = (const float*)d_in[13];
    const float* ow2 = (const float*)d_in[14];
    const float* ob2 = (const float*)d_in[15];
    const float* ow3 = (const float*)d_in[16];
    const float* ob3 = (const float*)d_in[17];
    const float* ow4 = (const float*)d_in[18];
    const float* ob4 = (const float*)d_in[19];
    float* out = (float*)d_out;

    zero_counts_kernel<<<(NN + 255) / 256, 256>>>();        // 1
    hist_kernel<<<(NE + 255) / 256, 256>>>(ei);             // 2
    scan_kernel<<<1, SCAN_T>>>();                           // 3
    fill_kernel<<<(NE + 255) / 256, 256>>>(ei);             // 4
    zero_pooled_kernel<<<1, 1024>>>();                      // 5
    gather_kernel<<<(NN + 7) / 8, 256>>>(x, ei, ea, ew1, eb1);  // 6 <- ncu capture
    node_fused_kernel<<<(NN + 127) / 128, 128>>>(x, batch,
        ew2, eb2, nw1, nb1, nw2, nb2);                      // 7
    out_kernel<<<1, NG * HH>>>(ow1, ob1, ow2, ob2, ow3, ob3, ow4, ob4, out);  // 8
}

// round 6
// speedup vs baseline: 1.4678x; 1.0937x over previous
#include <cuda_runtime.h>

#define NN 50000
#define NE 1600000
#define HH 64
#define NG 16
#define DOUT 2

#define VPAD 68   // svec row stride (floats): conflict-free LDS.128 at lane stride 68

// Scratch (device globals; zero-initialized at module load; tail kernel re-zeros)
__device__ __align__(16) float g_relu_sum[NN * HH];
__device__ __align__(16) float g_pooled[NG * HH];
__device__ int g_count[NN];
__device__ int g_off[NN];
__device__ int g_cur[NN];
__device__ int g_eidx[NE];

// ---------------------------------------------------------------------------
__global__ void __launch_bounds__(256) hist_kernel(const int* __restrict__ ei) {
    int e = blockIdx.x * 256 + threadIdx.x;
    if (e >= NE) return;
    atomicAdd(&g_count[ei[NE + e]], 1);
}

// ---------------------------------------------------------------------------
// Single-block exclusive scan of g_count -> g_off, g_cur.
#define SCAN_T 1024
#define SCAN_ITEMS 49   // 1024*49 = 50176 >= 50000
__global__ void __launch_bounds__(SCAN_T) scan_kernel() {
    __shared__ int sd[SCAN_T];
    int t = threadIdx.x;
    int base = t * SCAN_ITEMS;

    int loc[SCAN_ITEMS];
    int sum = 0;
#pragma unroll
    for (int i = 0; i < SCAN_ITEMS; i++) {
        int idx = base + i;
        int v = (idx < NN) ? g_count[idx] : 0;
        loc[i] = sum;
        sum += v;
    }
    sd[t] = sum;
    __syncthreads();
#pragma unroll
    for (int d = 1; d < SCAN_T; d <<= 1) {
        int u = (t >= d) ? sd[t - d] : 0;
        __syncthreads();
        sd[t] += u;
        __syncthreads();
    }
    int tbase = sd[t] - sum;
#pragma unroll
    for (int i = 0; i < SCAN_ITEMS; i++) {
        int idx = base + i;
        if (idx < NN) {
            int o = tbase + loc[i];
            g_off[idx] = o;
            g_cur[idx] = o;
        }
    }
}

// ---------------------------------------------------------------------------
__global__ void __launch_bounds__(256) fill_kernel(const int* __restrict__ ei) {
    int e = blockIdx.x * 256 + threadIdx.x;
    if (e >= NE) return;
    int c = ei[NE + e];
    int p = atomicAdd(&g_cur[c], 1);
    g_eidx[p] = e;
}

// ---------------------------------------------------------------------------
// Gather: warp per node; smem float4 stage; one broadcast LDS.128 per edge.
__global__ void __launch_bounds__(256) gather_kernel(
    const float* __restrict__ x,
    const int* __restrict__ ei,
    const float* __restrict__ ea,
    const float* __restrict__ ew1,   // [5,64]
    const float* __restrict__ eb1)   // [64]
{
    __shared__ __align__(16) float4 stage[8][32];
    int warp = threadIdx.x >> 5, lane = threadIdx.x & 31;
    int n = blockIdx.x * 8 + warp;
    if (n >= NN) return;

    int start = g_off[n];
    int cnt   = g_count[n];
    float xc  = __ldg(&x[n]);

    int ja = lane, jb = lane + 32;
    float w0a = __ldg(&ew1[0 * 64 + ja]), w1a = __ldg(&ew1[1 * 64 + ja]);
    float w2a = __ldg(&ew1[2 * 64 + ja]), w3a = __ldg(&ew1[3 * 64 + ja]);
    float w4a = __ldg(&ew1[4 * 64 + ja]), ba  = __ldg(&eb1[ja]);
    float w0b = __ldg(&ew1[0 * 64 + jb]), w1b = __ldg(&ew1[1 * 64 + jb]);
    float w2b = __ldg(&ew1[2 * 64 + jb]), w3b = __ldg(&ew1[3 * 64 + jb]);
    float w4b = __ldg(&ew1[4 * 64 + jb]), bb  = __ldg(&eb1[jb]);

    float ca = fmaf(xc, w1a, ba);
    float cb = fmaf(xc, w1b, bb);

    float acc0 = 0.f, acc1 = 0.f;

    for (int g0 = 0; g0 < cnt; g0 += 32) {
        int idx = g0 + lane;
        float4 d = make_float4(0.f, 0.f, 0.f, 0.f);
        if (idx < cnt) {
            int e = g_eidx[start + idx];
            int r = __ldg(&ei[e]);
            d.x = __ldg(&x[r]);
            d.y = __ldg(&ea[3 * e + 0]);
            d.z = __ldg(&ea[3 * e + 1]);
            d.w = __ldg(&ea[3 * e + 2]);
        }
        stage[warp][lane] = d;
        __syncwarp();
        int m = min(32, cnt - g0);
#pragma unroll 4
        for (int k = 0; k < m; k++) {
            float4 s = stage[warp][k];
            float h0 = fmaf(s.x, w0a, fmaf(s.y, w2a, fmaf(s.z, w3a, fmaf(s.w, w4a, ca))));
            float h1 = fmaf(s.x, w0b, fmaf(s.y, w2b, fmaf(s.z, w3b, fmaf(s.w, w4b, cb))));
            acc0 += fmaxf(h0, 0.f);
            acc1 += fmaxf(h1, 0.f);
        }
        __syncwarp();
    }
    g_relu_sum[(size_t)n * HH + ja] = acc0;
    g_relu_sum[(size_t)n * HH + jb] = acc1;
}

// ---------------------------------------------------------------------------
__device__ __forceinline__ void fma4x4(float4& a, float4 iv, const float* wr) {
    float4 w0 = *(const float4*)(wr);
    float4 w1 = *(const float4*)(wr + 64);
    float4 w2 = *(const float4*)(wr + 128);
    float4 w3 = *(const float4*)(wr + 192);
    a.x = fmaf(iv.x, w0.x, a.x); a.y = fmaf(iv.x, w0.y, a.y);
    a.z = fmaf(iv.x, w0.z, a.z); a.w = fmaf(iv.x, w0.w, a.w);
    a.x = fmaf(iv.y, w1.x, a.x); a.y = fmaf(iv.y, w1.y, a.y);
    a.z = fmaf(iv.y, w1.z, a.z); a.w = fmaf(iv.y, w1.w, a.w);
    a.x = fmaf(iv.z, w2.x, a.x); a.y = fmaf(iv.z, w2.y, a.y);
    a.z = fmaf(iv.z, w2.z, a.z); a.w = fmaf(iv.z, w2.w, a.w);
    a.x = fmaf(iv.w, w3.x, a.x); a.y = fmaf(iv.w, w3.y, a.y);
    a.z = fmaf(iv.w, w3.z, a.z); a.w = fmaf(iv.w, w3.w, a.w);
}

// ---------------------------------------------------------------------------
// Fused node pipeline, spill-free: per-node 64-vector lives in padded smem
// (each thread owns its row); single float4[16] register accumulator.
// Dynamic smem: sw[65*64] | svec[128*VPAD] | sb[64] | spool[1024]
__global__ void __launch_bounds__(128) node_fused_kernel(
    const float* __restrict__ x,
    const int* __restrict__ batch,
    const float* __restrict__ ew2, const float* __restrict__ eb2,
    const float* __restrict__ nw1, const float* __restrict__ nb1,
    const float* __restrict__ nw2, const float* __restrict__ nb2)
{
    extern __shared__ __align__(16) float sm[];
    float* sw    = sm;                        // 4160 floats (max 65x64)
    float* svec  = sm + 4160;                 // 128*VPAD
    float* sb    = sm + 4160 + 128 * VPAD;    // 64
    float* spool = sb + 64;                   // 1024

    int tid = threadIdx.x;
    int base = blockIdx.x * 128;
    int n = base + tid;
    bool act = (n < NN);
    int nblk = min(128, NN - base);

    for (int i = tid; i < NG * HH; i += 128) spool[i] = 0.f;

    // Coalesced load of this block's relu_sum rows into svec
    const float4* gin = (const float4*)g_relu_sum + (size_t)base * 16;
    for (int i = tid; i < nblk * 16; i += 128) {
        int nn = i >> 4, kv = i & 15;
        *(float4*)&svec[nn * VPAD + kv * 4] = gin[i];
    }
    // Phase A weights
    for (int i = tid; i < 1024; i += 128) ((float4*)sw)[i] = ((const float4*)ew2)[i];
    if (tid < 64) sb[tid] = eb2[tid];
    __syncthreads();

    float dg = 0.f, xn = 0.f;
    int g = 0;
    if (act) {
        dg = (float)g_count[n];
        xn = __ldg(&x[n]);
        g  = batch[n];
    }

    float4 acc[16];
    float* myrow = &svec[tid * VPAD];

    // ---- Phase A: agg = deg*eb2 + relu_sum @ ew2 ----
    if (act) {
#pragma unroll
        for (int jv = 0; jv < 16; jv++)
            acc[jv] = make_float4(dg * sb[jv*4], dg * sb[jv*4+1],
                                  dg * sb[jv*4+2], dg * sb[jv*4+3]);
        for (int kv = 0; kv < 16; kv++) {
            float4 iv = *(const float4*)&myrow[kv * 4];
#pragma unroll
            for (int jv = 0; jv < 16; jv++)
                fma4x4(acc[jv], iv, &sw[kv * 4 * 64 + jv * 4]);
        }
#pragma unroll
        for (int jv = 0; jv < 16; jv++)
            *(float4*)&myrow[jv * 4] = acc[jv];   // own row only
    }
    __syncthreads();

    // Phase B weights
    for (int i = tid; i < 1040; i += 128) ((float4*)sw)[i] = ((const float4*)nw1)[i];
    if (tid < 64) sb[tid] = nb1[tid];
    __syncthreads();

    // ---- Phase B: t = relu(nb1 + x*nw1[0] + agg @ nw1[1:]) ----
    if (act) {
#pragma unroll
        for (int jv = 0; jv < 16; jv++)
            acc[jv] = make_float4(fmaf(xn, sw[jv*4+0], sb[jv*4+0]),
                                  fmaf(xn, sw[jv*4+1], sb[jv*4+1]),
                                  fmaf(xn, sw[jv*4+2], sb[jv*4+2]),
                                  fmaf(xn, sw[jv*4+3], sb[jv*4+3]));
        for (int kv = 0; kv < 16; kv++) {
            float4 iv = *(const float4*)&myrow[kv * 4];
#pragma unroll
            for (int jv = 0; jv < 16; jv++)
                fma4x4(acc[jv], iv, &sw[(kv * 4 + 1) * 64 + jv * 4]);
        }
#pragma unroll
        for (int jv = 0; jv < 16; jv++) {
            acc[jv].x = fmaxf(acc[jv].x, 0.f); acc[jv].y = fmaxf(acc[jv].y, 0.f);
            acc[jv].z = fmaxf(acc[jv].z, 0.f); acc[jv].w = fmaxf(acc[jv].w, 0.f);
            *(float4*)&myrow[jv * 4] = acc[jv];
        }
    }
    __syncthreads();

    // Phase C weights
    for (int i = tid; i < 1024; i += 128) ((float4*)sw)[i] = ((const float4*)nw2)[i];
    if (tid < 64) sb[tid] = nb2[tid];
    __syncthreads();

    // ---- Phase C: h = nb2 + t @ nw2; pool ----
    if (act) {
#pragma unroll
        for (int jv = 0; jv < 16; jv++)
            acc[jv] = make_float4(sb[jv*4], sb[jv*4+1], sb[jv*4+2], sb[jv*4+3]);
        for (int kv = 0; kv < 16; kv++) {
            float4 iv = *(const float4*)&myrow[kv * 4];
#pragma unroll
            for (int jv = 0; jv < 16; jv++)
                fma4x4(acc[jv], iv, &sw[kv * 4 * 64 + jv * 4]);
        }
#pragma unroll
        for (int jv = 0; jv < 16; jv++) {
            atomicAdd(&spool[g * HH + jv * 4 + 0], acc[jv].x);
            atomicAdd(&spool[g * HH + jv * 4 + 1], acc[jv].y);
            atomicAdd(&spool[g * HH + jv * 4 + 2], acc[jv].z);
            atomicAdd(&spool[g * HH + jv * 4 + 3], acc[jv].w);
        }
    }
    __syncthreads();
    for (int i = tid; i < NG * HH; i += 128)
        atomicAdd(&g_pooled[i], spool[i]);
}

// ---------------------------------------------------------------------------
// Head MLP: 3x (64->64 relu) + 64->2. One block of 1024 threads: (g, j).
__global__ void __launch_bounds__(1024) out_kernel(
    const float* __restrict__ ow1, const float* __restrict__ ob1,
    const float* __restrict__ ow2, const float* __restrict__ ob2,
    const float* __restrict__ ow3, const float* __restrict__ ob3,
    const float* __restrict__ ow4, const float* __restrict__ ob4,
    float* __restrict__ out)
{
    __shared__ float sa[NG * HH];
    __shared__ float sbuf[NG * HH];
    int tid = threadIdx.x;
    sa[tid] = g_pooled[tid];
    __syncthreads();

    int g = tid >> 6, j = tid & 63;

    float v = __ldg(&ob1[j]);
#pragma unroll 16
    for (int k = 0; k < 64; k++) v = fmaf(sa[g * 64 + k], __ldg(&ow1[k * 64 + j]), v);
    sbuf[tid] = fmaxf(v, 0.f);
    __syncthreads();

    v = __ldg(&ob2[j]);
#pragma unroll 16
    for (int k = 0; k < 64; k++) v = fmaf(sbuf[g * 64 + k], __ldg(&ow2[k * 64 + j]), v);
    sa[tid] = fmaxf(v, 0.f);
    __syncthreads();

    v = __ldg(&ob3[j]);
#pragma unroll 16
    for (int k = 0; k < 64; k++) v = fmaf(sa[g * 64 + k], __ldg(&ow3[k * 64 + j]), v);
    sbuf[tid] = fmaxf(v, 0.f);
    __syncthreads();

    if (j < DOUT) {
        float o = __ldg(&ob4[j]);
#pragma unroll 16
        for (int k = 0; k < 64; k++)
            o = fmaf(sbuf[g * 64 + k], __ldg(&ow4[k * DOUT + j]), o);
        out[g * DOUT + j] = o;
    }
}

// ---------------------------------------------------------------------------
// Tail: restore zeroed state for the next graph replay (and idempotent on
// the correctness call, where CUDA zero-init provided the initial state).
__global__ void tail_zero_kernel() {
    int i = blockIdx.x * blockDim.x + threadIdx.x;
    if (i < NN) g_count[i] = 0;
    if (i < NG * HH) g_pooled[i] = 0.f;
}

// ---------------------------------------------------------------------------
extern "C" void kernel_launch(void* const* d_in, const int* in_sizes, int n_in,
                              void* d_out, int out_size) {
    const float* x     = (const float*)d_in[0];
    const int* ei      = (const int*)d_in[1];
    const float* ea    = (const float*)d_in[2];
    const int* batch   = (const int*)d_in[3];
    const float* ew1 = (const float*)d_in[4];
    const float* eb1 = (const float*)d_in[5];
    const float* ew2 = (const float*)d_in[6];
    const float* eb2 = (const float*)d_in[7];
    const float* nw1 = (const float*)d_in[8];
    const float* nb1 = (const float*)d_in[9];
    const float* nw2 = (const float*)d_in[10];
    const float* nb2 = (const float*)d_in[11];
    const float* ow1 = (const float*)d_in[12];
    const float* ob1 = (const float*)d_in[13];
    const float* ow2 = (const float*)d_in[14];
    const float* ob2 = (const float*)d_in[15];
    const float* ow3 = (const float*)d_in[16];
    const float* ob3 = (const float*)d_in[17];
    const float* ow4 = (const float*)d_in[18];
    const float* ob4 = (const float*)d_in[19];
    float* out = (float*)d_out;

    const int node_smem = (4160 + 128 * VPAD + 64 + 1024) * 4;   // 55808 B
    static int smem_set = 0;
    if (!smem_set) {
        cudaFuncSetAttribute(node_fused_kernel,
                             cudaFuncAttributeMaxDynamicSharedMemorySize, node_smem);
        smem_set = 1;
    }

    hist_kernel<<<(NE + 255) / 256, 256>>>(ei);                 // 1
    scan_kernel<<<1, SCAN_T>>>();                               // 2
    fill_kernel<<<(NE + 255) / 256, 256>>>(ei);                 // 3
    gather_kernel<<<(NN + 7) / 8, 256>>>(x, ei, ea, ew1, eb1);  // 4 <- ncu
    node_fused_kernel<<<(NN + 127) / 128, 128, node_smem>>>(x, batch,
        ew2, eb2, nw1, nb1, nw2, nb2);                          // 5
    out_kernel<<<1, NG * HH>>>(ow1, ob1, ow2, ob2, ow3, ob3, ow4, ob4, out); // 6
    tail_zero_kernel<<<(NN + 255) / 256, 256>>>();              // 7
}

// round 7
// speedup vs baseline: 1.7665x; 1.2035x over previous
#include <cuda_runtime.h>

#define NN 50000
#define NE 1600000
#define HH 64
#define NG 16
#define DOUT 2

#define VPAD 68   // svec row stride (floats): conflict-free LDS.128

#define SCAN_T 1024
#define NB_SCAN ((NN + SCAN_T - 1) / SCAN_T)   // 49

// Scratch (device globals; zero-initialized at load; head kernel re-zeros)
__device__ __align__(16) float g_relu_sum[NN * HH];
__device__ __align__(16) float g_pooled[NG * HH];
__device__ __align__(16) float4 g_edata[NE];     // packed (x[row], a0, a1, a2) per CSR slot
__device__ int g_count[NN];
__device__ int g_off[NN];
__device__ int g_cur[NN];
__device__ int g_bsum[NB_SCAN];

// ---------------------------------------------------------------------------
__global__ void zero_kernel() {
    int i = blockIdx.x * blockDim.x + threadIdx.x;
    if (i < NN) g_count[i] = 0;
    if (i < NG * HH) g_pooled[i] = 0.f;
}

// ---------------------------------------------------------------------------
// Histogram of destinations; 4 edges per thread via int4.
__global__ void __launch_bounds__(256) hist_kernel(const int* __restrict__ ei) {
    int t = blockIdx.x * 256 + threadIdx.x;
    int e4 = t * 4;
    if (e4 >= NE) return;
    int4 c = *(const int4*)&ei[NE + e4];   // NE % 4 == 0 -> aligned
    atomicAdd(&g_count[c.x], 1);
    atomicAdd(&g_count[c.y], 1);
    atomicAdd(&g_count[c.z], 1);
    atomicAdd(&g_count[c.w], 1);
}

// ---------------------------------------------------------------------------
// scanA: 49 blocks x 1024 threads, one element each. Coalesced. Block-local
// exclusive prefix -> g_off, block total -> g_bsum.
__global__ void __launch_bounds__(SCAN_T) scanA_kernel() {
    __shared__ int sd[SCAN_T];
    int t = threadIdx.x;
    int i = blockIdx.x * SCAN_T + t;
    int v = (i < NN) ? g_count[i] : 0;
    sd[t] = v;
    __syncthreads();
#pragma unroll
    for (int d = 1; d < SCAN_T; d <<= 1) {
        int u = (t >= d) ? sd[t - d] : 0;
        __syncthreads();
        sd[t] += u;
        __syncthreads();
    }
    if (i < NN) g_off[i] = sd[t] - v;               // exclusive within block
    if (t == SCAN_T - 1) g_bsum[blockIdx.x] = sd[t];
}

// scanC: each block redundantly prefixes the 49 block totals (tiny), adds
// its base, writes final g_off and g_cur. Coalesced.
__global__ void __launch_bounds__(SCAN_T) scanC_kernel() {
    __shared__ int sbase;
    int t = threadIdx.x;
    if (t == 0) {
        int b = 0;
        for (int j = 0; j < (int)blockIdx.x; j++) b += g_bsum[j];
        sbase = b;
    }
    __syncthreads();
    int i = blockIdx.x * SCAN_T + t;
    if (i < NN) {
        int o = g_off[i] + sbase;
        g_off[i] = o;
        g_cur[i] = o;
    }
}

// ---------------------------------------------------------------------------
// Fill CSR slots with PACKED edge data: (x[row], a0, a1, a2).
__global__ void __launch_bounds__(256) fill_kernel(
    const int* __restrict__ ei,
    const float* __restrict__ x,
    const float* __restrict__ ea)
{
    int e = blockIdx.x * 256 + threadIdx.x;
    if (e >= NE) return;
    int c = ei[NE + e];
    int p = atomicAdd(&g_cur[c], 1);
    int r = __ldg(&ei[e]);
    float xr = __ldg(&x[r]);
    float a0 = __ldg(&ea[3 * e + 0]);
    float a1 = __ldg(&ea[3 * e + 1]);
    float a2 = __ldg(&ea[3 * e + 2]);
    g_edata[p] = make_float4(xr, a0, a1, a2);
}

// ---------------------------------------------------------------------------
// Gather: warp per node; ONE coalesced float4 load per edge; smem broadcast.
__global__ void __launch_bounds__(256) gather_kernel(
    const float* __restrict__ x,
    const float* __restrict__ ew1,   // [5,64]
    const float* __restrict__ eb1)   // [64]
{
    __shared__ __align__(16) float4 stage[8][32];
    int warp = threadIdx.x >> 5, lane = threadIdx.x & 31;
    int n = blockIdx.x * 8 + warp;
    if (n >= NN) return;

    int start = g_off[n];
    int cnt   = g_count[n];
    float xc  = __ldg(&x[n]);

    int ja = lane, jb = lane + 32;
    float w0a = __ldg(&ew1[0 * 64 + ja]), w1a = __ldg(&ew1[1 * 64 + ja]);
    float w2a = __ldg(&ew1[2 * 64 + ja]), w3a = __ldg(&ew1[3 * 64 + ja]);
    float w4a = __ldg(&ew1[4 * 64 + ja]), ba  = __ldg(&eb1[ja]);
    float w0b = __ldg(&ew1[0 * 64 + jb]), w1b = __ldg(&ew1[1 * 64 + jb]);
    float w2b = __ldg(&ew1[2 * 64 + jb]), w3b = __ldg(&ew1[3 * 64 + jb]);
    float w4b = __ldg(&ew1[4 * 64 + jb]), bb  = __ldg(&eb1[jb]);

    float ca = fmaf(xc, w1a, ba);
    float cb = fmaf(xc, w1b, bb);

    float acc0 = 0.f, acc1 = 0.f;

    for (int g0 = 0; g0 < cnt; g0 += 32) {
        int idx = g0 + lane;
        float4 d = make_float4(0.f, 0.f, 0.f, 0.f);
        if (idx < cnt) d = g_edata[start + idx];   // coalesced LDG.128
        stage[warp][lane] = d;
        __syncwarp();
        int m = min(32, cnt - g0);
#pragma unroll 4
        for (int k = 0; k < m; k++) {
            float4 s = stage[warp][k];             // broadcast LDS.128
            float h0 = fmaf(s.x, w0a, fmaf(s.y, w2a, fmaf(s.z, w3a, fmaf(s.w, w4a, ca))));
            float h1 = fmaf(s.x, w0b, fmaf(s.y, w2b, fmaf(s.z, w3b, fmaf(s.w, w4b, cb))));
            acc0 += fmaxf(h0, 0.f);
            acc1 += fmaxf(h1, 0.f);
        }
        __syncwarp();
    }
    g_relu_sum[(size_t)n * HH + ja] = acc0;
    g_relu_sum[(size_t)n * HH + jb] = acc1;
}

// ---------------------------------------------------------------------------
__device__ __forceinline__ void fma4x4(float4& a, float4 iv, const float* wr) {
    float4 w0 = *(const float4*)(wr);
    float4 w1 = *(const float4*)(wr + 64);
    float4 w2 = *(const float4*)(wr + 128);
    float4 w3 = *(const float4*)(wr + 192);
    a.x = fmaf(iv.x, w0.x, a.x); a.y = fmaf(iv.x, w0.y, a.y);
    a.z = fmaf(iv.x, w0.z, a.z); a.w = fmaf(iv.x, w0.w, a.w);
    a.x = fmaf(iv.y, w1.x, a.x); a.y = fmaf(iv.y, w1.y, a.y);
    a.z = fmaf(iv.y, w1.z, a.z); a.w = fmaf(iv.y, w1.w, a.w);
    a.x = fmaf(iv.z, w2.x, a.x); a.y = fmaf(iv.z, w2.y, a.y);
    a.z = fmaf(iv.z, w2.z, a.z); a.w = fmaf(iv.z, w2.w, a.w);
    a.x = fmaf(iv.w, w3.x, a.x); a.y = fmaf(iv.w, w3.y, a.y);
    a.z = fmaf(iv.w, w3.z, a.z); a.w = fmaf(iv.w, w3.w, a.w);
}

// ---------------------------------------------------------------------------
// Fused node pipeline (spill-free via padded smem vector rows).
__global__ void __launch_bounds__(128) node_fused_kernel(
    const float* __restrict__ x,
    const int* __restrict__ batch,
    const float* __restrict__ ew2, const float* __restrict__ eb2,
    const float* __restrict__ nw1, const float* __restrict__ nb1,
    const float* __restrict__ nw2, const float* __restrict__ nb2)
{
    extern __shared__ __align__(16) float sm[];
    float* sw    = sm;                        // 4160 floats
    float* svec  = sm + 4160;                 // 128*VPAD
    float* sb    = sm + 4160 + 128 * VPAD;    // 64
    float* spool = sb + 64;                   // 1024

    int tid = threadIdx.x;
    int base = blockIdx.x * 128;
    int n = base + tid;
    bool act = (n < NN);
    int nblk = min(128, NN - base);

    for (int i = tid; i < NG * HH; i += 128) spool[i] = 0.f;

    const float4* gin = (const float4*)g_relu_sum + (size_t)base * 16;
    for (int i = tid; i < nblk * 16; i += 128) {
        int nn = i >> 4, kv = i & 15;
        *(float4*)&svec[nn * VPAD + kv * 4] = gin[i];
    }
    for (int i = tid; i < 1024; i += 128) ((float4*)sw)[i] = ((const float4*)ew2)[i];
    if (tid < 64) sb[tid] = eb2[tid];
    __syncthreads();

    float dg = 0.f, xn = 0.f;
    int g = 0;
    if (act) {
        dg = (float)g_count[n];
        xn = __ldg(&x[n]);
        g  = batch[n];
    }

    float4 acc[16];
    float* myrow = &svec[tid * VPAD];

    // Phase A
    if (act) {
#pragma unroll
        for (int jv = 0; jv < 16; jv++)
            acc[jv] = make_float4(dg * sb[jv*4], dg * sb[jv*4+1],
                                  dg * sb[jv*4+2], dg * sb[jv*4+3]);
        for (int kv = 0; kv < 16; kv++) {
            float4 iv = *(const float4*)&myrow[kv * 4];
#pragma unroll
            for (int jv = 0; jv < 16; jv++)
                fma4x4(acc[jv], iv, &sw[kv * 4 * 64 + jv * 4]);
        }
#pragma unroll
        for (int jv = 0; jv < 16; jv++)
            *(float4*)&myrow[jv * 4] = acc[jv];
    }
    __syncthreads();

    for (int i = tid; i < 1040; i += 128) ((float4*)sw)[i] = ((const float4*)nw1)[i];
    if (tid < 64) sb[tid] = nb1[tid];
    __syncthreads();

    // Phase B
    if (act) {
#pragma unroll
        for (int jv = 0; jv < 16; jv++)
            acc[jv] = make_float4(fmaf(xn, sw[jv*4+0], sb[jv*4+0]),
                                  fmaf(xn, sw[jv*4+1], sb[jv*4+1]),
                                  fmaf(xn, sw[jv*4+2], sb[jv*4+2]),
                                  fmaf(xn, sw[jv*4+3], sb[jv*4+3]));
        for (int kv = 0; kv < 16; kv++) {
            float4 iv = *(const float4*)&myrow[kv * 4];
#pragma unroll
            for (int jv = 0; jv < 16; jv++)
                fma4x4(acc[jv], iv, &sw[(kv * 4 + 1) * 64 + jv * 4]);
        }
#pragma unroll
        for (int jv = 0; jv < 16; jv++) {
            acc[jv].x = fmaxf(acc[jv].x, 0.f); acc[jv].y = fmaxf(acc[jv].y, 0.f);
            acc[jv].z = fmaxf(acc[jv].z, 0.f); acc[jv].w = fmaxf(acc[jv].w, 0.f);
            *(float4*)&myrow[jv * 4] = acc[jv];
        }
    }
    __syncthreads();

    for (int i = tid; i < 1024; i += 128) ((float4*)sw)[i] = ((const float4*)nw2)[i];
    if (tid < 64) sb[tid] = nb2[tid];
    __syncthreads();

    // Phase C + pool
    if (act) {
#pragma unroll
        for (int jv = 0; jv < 16; jv++)
            acc[jv] = make_float4(sb[jv*4], sb[jv*4+1], sb[jv*4+2], sb[jv*4+3]);
        for (int kv = 0; kv < 16; kv++) {
            float4 iv = *(const float4*)&myrow[kv * 4];
#pragma unroll
            for (int jv = 0; jv < 16; jv++)
                fma4x4(acc[jv], iv, &sw[kv * 4 * 64 + jv * 4]);
        }
#pragma unroll
        for (int jv = 0; jv < 16; jv++) {
            atomicAdd(&spool[g * HH + jv * 4 + 0], acc[jv].x);
            atomicAdd(&spool[g * HH + jv * 4 + 1], acc[jv].y);
            atomicAdd(&spool[g * HH + jv * 4 + 2], acc[jv].z);
            atomicAdd(&spool[g * HH + jv * 4 + 3], acc[jv].w);
        }
    }
    __syncthreads();
    for (int i = tid; i < NG * HH; i += 128)
        atomicAdd(&g_pooled[i], spool[i]);
}

// ---------------------------------------------------------------------------
// Head MLP
__global__ void __launch_bounds__(1024) out_kernel(
    const float* __restrict__ ow1, const float* __restrict__ ob1,
    const float* __restrict__ ow2, const float* __restrict__ ob2,
    const float* __restrict__ ow3, const float* __restrict__ ob3,
    const float* __restrict__ ow4, const float* __restrict__ ob4,
    float* __restrict__ out)
{
    __shared__ float sa[NG * HH];
    __shared__ float sbuf[NG * HH];
    int tid = threadIdx.x;
    sa[tid] = g_pooled[tid];
    __syncthreads();

    int g = tid >> 6, j = tid & 63;

    float v = __ldg(&ob1[j]);
#pragma unroll 16
    for (int k = 0; k < 64; k++) v = fmaf(sa[g * 64 + k], __ldg(&ow1[k * 64 + j]), v);
    sbuf[tid] = fmaxf(v, 0.f);
    __syncthreads();

    v = __ldg(&ob2[j]);
#pragma unroll 16
    for (int k = 0; k < 64; k++) v = fmaf(sbuf[g * 64 + k], __ldg(&ow2[k * 64 + j]), v);
    sa[tid] = fmaxf(v, 0.f);
    __syncthreads();

    v = __ldg(&ob3[j]);
#pragma unroll 16
    for (int k = 0; k < 64; k++) v = fmaf(sa[g * 64 + k], __ldg(&ow3[k * 64 + j]), v);
    sbuf[tid] = fmaxf(v, 0.f);
    __syncthreads();

    if (j < DOUT) {
        float o = __ldg(&ob4[j]);
#pragma unroll 16
        for (int k = 0; k < 64; k++)
            o = fmaf(sbuf[g * 64 + k], __ldg(&ow4[k * DOUT + j]), o);
        out[g * DOUT + j] = o;
    }
}

// ---------------------------------------------------------------------------
extern "C" void kernel_launch(void* const* d_in, const int* in_sizes, int n_in,
                              void* d_out, int out_size) {
    const float* x     = (const float*)d_in[0];
    const int* ei      = (const int*)d_in[1];
    const float* ea    = (const float*)d_in[2];
    const int* batch   = (const int*)d_in[3];
    const float* ew1 = (const float*)d_in[4];
    const float* eb1 = (const float*)d_in[5];
    const float* ew2 = (const float*)d_in[6];
    const float* eb2 = (const float*)d_in[7];
    const float* nw1 = (const float*)d_in[8];
    const float* nb1 = (const float*)d_in[9];
    const float* nw2 = (const float*)d_in[10];
    const float* nb2 = (const float*)d_in[11];
    const float* ow1 = (const float*)d_in[12];
    const float* ob1 = (const float*)d_in[13];
    const float* ow2 = (const float*)d_in[14];
    const float* ob2 = (const float*)d_in[15];
    const float* ow3 = (const float*)d_in[16];
    const float* ob3 = (const float*)d_in[17];
    const float* ow4 = (const float*)d_in[18];
    const float* ob4 = (const float*)d_in[19];
    float* out = (float*)d_out;

    const int node_smem = (4160 + 128 * VPAD + 64 + 1024) * 4;   // 55808 B
    static int smem_set = 0;
    if (!smem_set) {
        cudaFuncSetAttribute(node_fused_kernel,
                             cudaFuncAttributeMaxDynamicSharedMemorySize, node_smem);
        smem_set = 1;
    }

    zero_kernel<<<(NN + 255) / 256, 256>>>();                    // 1
    hist_kernel<<<(NE / 4 + 255) / 256, 256>>>(ei);              // 2
    scanA_kernel<<<NB_SCAN, SCAN_T>>>();                         // 3
    scanC_kernel<<<NB_SCAN, SCAN_T>>>();                         // 4 <- ncu
    fill_kernel<<<(NE + 255) / 256, 256>>>(ei, x, ea);           // 5
    gather_kernel<<<(NN + 7) / 8, 256>>>(x, ew1, eb1);           // 6
    node_fused_kernel<<<(NN + 127) / 128, 128, node_smem>>>(x, batch,
        ew2, eb2, nw1, nb1, nw2, nb2);                           // 7
    out_kernel<<<1, NG * HH>>>(ow1, ob1, ow2, ob2, ow3, ob3, ow4, ob4, out); // 8
}

// round 8
// speedup vs baseline: 1.8036x; 1.0210x over previous
#include <cuda_runtime.h>

#define NN 50000
#define NE 1600000
#define HH 64
#define NG 16
#define DOUT 2

#define VPAD 68   // svec row stride (floats): conflict-free LDS.128

#define SCAN_T 1024
#define NB_SCAN ((NN + SCAN_T - 1) / SCAN_T)   // 49

// Scratch (device globals; zero-initialized at load; kernels tail-zero state)
__device__ __align__(16) float g_relu_sum[NN * HH];
__device__ __align__(16) float g_pooled[NG * HH];
__device__ __align__(16) float4 g_edata[NE];     // packed (x[row], a0, a1, a2) per CSR slot
__device__ int g_count[NN];
__device__ int g_off[NN];
__device__ int g_cur[NN];

// ---------------------------------------------------------------------------
// Histogram of destinations; 4 edges per thread via int4.
__global__ void __launch_bounds__(256) hist_kernel(const int* __restrict__ ei) {
    int t = blockIdx.x * 256 + threadIdx.x;
    int e4 = t * 4;
    if (e4 >= NE) return;
    int4 c = *(const int4*)&ei[NE + e4];   // NE % 4 == 0 -> aligned
    atomicAdd(&g_count[c.x], 1);
    atomicAdd(&g_count[c.y], 1);
    atomicAdd(&g_count[c.z], 1);
    atomicAdd(&g_count[c.w], 1);
}

// ---------------------------------------------------------------------------
// Fused scan: each block redundantly reduces g_count[0..base) for its base
// (coalesced, no cross-block sync), then exclusive-scans its own segment.
__global__ void __launch_bounds__(SCAN_T) scan_kernel() {
    __shared__ int sd[SCAN_T];
    __shared__ int sbase;
    int t = threadIdx.x;
    int seg0 = blockIdx.x * SCAN_T;

    // 1) base = sum of g_count[0 .. seg0)
    int part = 0;
    for (int i = t; i < seg0; i += SCAN_T) part += g_count[i];
    // block reduce
    sd[t] = part;
    __syncthreads();
#pragma unroll
    for (int d = SCAN_T / 2; d >= 32; d >>= 1) {
        if (t < d) sd[t] += sd[t + d];
        __syncthreads();
    }
    if (t < 32) {
        int v = sd[t];
#pragma unroll
        for (int o = 16; o > 0; o >>= 1) v += __shfl_down_sync(0xffffffffu, v, o);
        if (t == 0) sbase = v;
    }
    __syncthreads();
    int base = sbase;
    __syncthreads();   // sd reuse below

    // 2) exclusive scan of own segment
    int i = seg0 + t;
    int v = (i < NN) ? g_count[i] : 0;
    sd[t] = v;
    __syncthreads();
#pragma unroll
    for (int d = 1; d < SCAN_T; d <<= 1) {
        int u = (t >= d) ? sd[t - d] : 0;
        __syncthreads();
        sd[t] += u;
        __syncthreads();
    }
    if (i < NN) {
        int o = base + sd[t] - v;
        g_off[i] = o;
        g_cur[i] = o;
    }
}

// ---------------------------------------------------------------------------
// Fill CSR slots with PACKED edge data: (x[row], a0, a1, a2).
__global__ void __launch_bounds__(256) fill_kernel(
    const int* __restrict__ ei,
    const float* __restrict__ x,
    const float* __restrict__ ea)
{
    int e = blockIdx.x * 256 + threadIdx.x;
    if (e >= NE) return;
    int c = ei[NE + e];
    int p = atomicAdd(&g_cur[c], 1);
    int r = __ldg(&ei[e]);
    float xr = __ldg(&x[r]);
    float a0 = __ldg(&ea[3 * e + 0]);
    float a1 = __ldg(&ea[3 * e + 1]);
    float a2 = __ldg(&ea[3 * e + 2]);
    g_edata[p] = make_float4(xr, a0, a1, a2);
}

// ---------------------------------------------------------------------------
// Gather: warp per node; ONE coalesced float4 load per edge; smem broadcast.
__global__ void __launch_bounds__(256) gather_kernel(
    const float* __restrict__ x,
    const float* __restrict__ ew1,   // [5,64]
    const float* __restrict__ eb1)   // [64]
{
    __shared__ __align__(16) float4 stage[8][32];
    int warp = threadIdx.x >> 5, lane = threadIdx.x & 31;
    int n = blockIdx.x * 8 + warp;
    if (n >= NN) return;

    int start = g_off[n];
    int cnt   = g_count[n];
    float xc  = __ldg(&x[n]);

    int ja = lane, jb = lane + 32;
    float w0a = __ldg(&ew1[0 * 64 + ja]), w1a = __ldg(&ew1[1 * 64 + ja]);
    float w2a = __ldg(&ew1[2 * 64 + ja]), w3a = __ldg(&ew1[3 * 64 + ja]);
    float w4a = __ldg(&ew1[4 * 64 + ja]), ba  = __ldg(&eb1[ja]);
    float w0b = __ldg(&ew1[0 * 64 + jb]), w1b = __ldg(&ew1[1 * 64 + jb]);
    float w2b = __ldg(&ew1[2 * 64 + jb]), w3b = __ldg(&ew1[3 * 64 + jb]);
    float w4b = __ldg(&ew1[4 * 64 + jb]), bb  = __ldg(&eb1[jb]);

    float ca = fmaf(xc, w1a, ba);
    float cb = fmaf(xc, w1b, bb);

    float acc0 = 0.f, acc1 = 0.f;

    for (int g0 = 0; g0 < cnt; g0 += 32) {
        int idx = g0 + lane;
        float4 d = make_float4(0.f, 0.f, 0.f, 0.f);
        if (idx < cnt) d = g_edata[start + idx];   // coalesced LDG.128
        stage[warp][lane] = d;
        __syncwarp();
        int m = min(32, cnt - g0);
#pragma unroll 4
        for (int k = 0; k < m; k++) {
            float4 s = stage[warp][k];             // broadcast LDS.128
            float h0 = fmaf(s.x, w0a, fmaf(s.y, w2a, fmaf(s.z, w3a, fmaf(s.w, w4a, ca))));
            float h1 = fmaf(s.x, w0b, fmaf(s.y, w2b, fmaf(s.z, w3b, fmaf(s.w, w4b, cb))));
            acc0 += fmaxf(h0, 0.f);
            acc1 += fmaxf(h1, 0.f);
        }
        __syncwarp();
    }
    g_relu_sum[(size_t)n * HH + ja] = acc0;
    g_relu_sum[(size_t)n * HH + jb] = acc1;
}

// ---------------------------------------------------------------------------
__device__ __forceinline__ void fma4x4(float4& a, float4 iv, const float* wr) {
    float4 w0 = *(const float4*)(wr);
    float4 w1 = *(const float4*)(wr + 64);
    float4 w2 = *(const float4*)(wr + 128);
    float4 w3 = *(const float4*)(wr + 192);
    a.x = fmaf(iv.x, w0.x, a.x); a.y = fmaf(iv.x, w0.y, a.y);
    a.z = fmaf(iv.x, w0.z, a.z); a.w = fmaf(iv.x, w0.w, a.w);
    a.x = fmaf(iv.y, w1.x, a.x); a.y = fmaf(iv.y, w1.y, a.y);
    a.z = fmaf(iv.y, w1.z, a.z); a.w = fmaf(iv.y, w1.w, a.w);
    a.x = fmaf(iv.z, w2.x, a.x); a.y = fmaf(iv.z, w2.y, a.y);
    a.z = fmaf(iv.z, w2.z, a.z); a.w = fmaf(iv.z, w2.w, a.w);
    a.x = fmaf(iv.w, w3.x, a.x); a.y = fmaf(iv.w, w3.y, a.y);
    a.z = fmaf(iv.w, w3.z, a.z); a.w = fmaf(iv.w, w3.w, a.w);
}

// ---------------------------------------------------------------------------
// Fused node pipeline (spill-free via padded smem vector rows).
// Tail-zeroes g_count after its final read (last consumer).
__global__ void __launch_bounds__(128) node_fused_kernel(
    const float* __restrict__ x,
    const int* __restrict__ batch,
    const float* __restrict__ ew2, const float* __restrict__ eb2,
    const float* __restrict__ nw1, const float* __restrict__ nb1,
    const float* __restrict__ nw2, const float* __restrict__ nb2)
{
    extern __shared__ __align__(16) float sm[];
    float* sw    = sm;                        // 4160 floats
    float* svec  = sm + 4160;                 // 128*VPAD
    float* sb    = sm + 4160 + 128 * VPAD;    // 64
    float* spool = sb + 64;                   // 1024

    int tid = threadIdx.x;
    int base = blockIdx.x * 128;
    int n = base + tid;
    bool act = (n < NN);
    int nblk = min(128, NN - base);

    for (int i = tid; i < NG * HH; i += 128) spool[i] = 0.f;

    const float4* gin = (const float4*)g_relu_sum + (size_t)base * 16;
    for (int i = tid; i < nblk * 16; i += 128) {
        int nn = i >> 4, kv = i & 15;
        *(float4*)&svec[nn * VPAD + kv * 4] = gin[i];
    }
    for (int i = tid; i < 1024; i += 128) ((float4*)sw)[i] = ((const float4*)ew2)[i];
    if (tid < 64) sb[tid] = eb2[tid];
    __syncthreads();

    float dg = 0.f, xn = 0.f;
    int g = 0;
    if (act) {
        dg = (float)g_count[n];
        g_count[n] = 0;                 // tail-zero for next replay
        xn = __ldg(&x[n]);
        g  = batch[n];
    }

    float4 acc[16];
    float* myrow = &svec[tid * VPAD];

    // Phase A: agg = deg*eb2 + relu_sum @ ew2
    if (act) {
#pragma unroll
        for (int jv = 0; jv < 16; jv++)
            acc[jv] = make_float4(dg * sb[jv*4], dg * sb[jv*4+1],
                                  dg * sb[jv*4+2], dg * sb[jv*4+3]);
        for (int kv = 0; kv < 16; kv++) {
            float4 iv = *(const float4*)&myrow[kv * 4];
#pragma unroll
            for (int jv = 0; jv < 16; jv++)
                fma4x4(acc[jv], iv, &sw[kv * 4 * 64 + jv * 4]);
        }
#pragma unroll
        for (int jv = 0; jv < 16; jv++)
            *(float4*)&myrow[jv * 4] = acc[jv];
    }
    __syncthreads();

    for (int i = tid; i < 1040; i += 128) ((float4*)sw)[i] = ((const float4*)nw1)[i];
    if (tid < 64) sb[tid] = nb1[tid];
    __syncthreads();

    // Phase B: t = relu(nb1 + x*nw1[0] + agg @ nw1[1:])
    if (act) {
#pragma unroll
        for (int jv = 0; jv < 16; jv++)
            acc[jv] = make_float4(fmaf(xn, sw[jv*4+0], sb[jv*4+0]),
                                  fmaf(xn, sw[jv*4+1], sb[jv*4+1]),
                                  fmaf(xn, sw[jv*4+2], sb[jv*4+2]),
                                  fmaf(xn, sw[jv*4+3], sb[jv*4+3]));
        for (int kv = 0; kv < 16; kv++) {
            float4 iv = *(const float4*)&myrow[kv * 4];
#pragma unroll
            for (int jv = 0; jv < 16; jv++)
                fma4x4(acc[jv], iv, &sw[(kv * 4 + 1) * 64 + jv * 4]);
        }
#pragma unroll
        for (int jv = 0; jv < 16; jv++) {
            acc[jv].x = fmaxf(acc[jv].x, 0.f); acc[jv].y = fmaxf(acc[jv].y, 0.f);
            acc[jv].z = fmaxf(acc[jv].z, 0.f); acc[jv].w = fmaxf(acc[jv].w, 0.f);
            *(float4*)&myrow[jv * 4] = acc[jv];
        }
    }
    __syncthreads();

    for (int i = tid; i < 1024; i += 128) ((float4*)sw)[i] = ((const float4*)nw2)[i];
    if (tid < 64) sb[tid] = nb2[tid];
    __syncthreads();

    // Phase C: h = nb2 + t @ nw2; pool
    if (act) {
#pragma unroll
        for (int jv = 0; jv < 16; jv++)
            acc[jv] = make_float4(sb[jv*4], sb[jv*4+1], sb[jv*4+2], sb[jv*4+3]);
        for (int kv = 0; kv < 16; kv++) {
            float4 iv = *(const float4*)&myrow[kv * 4];
#pragma unroll
            for (int jv = 0; jv < 16; jv++)
                fma4x4(acc[jv], iv, &sw[kv * 4 * 64 + jv * 4]);
        }
#pragma unroll
        for (int jv = 0; jv < 16; jv++) {
            atomicAdd(&spool[g * HH + jv * 4 + 0], acc[jv].x);
            atomicAdd(&spool[g * HH + jv * 4 + 1], acc[jv].y);
            atomicAdd(&spool[g * HH + jv * 4 + 2], acc[jv].z);
            atomicAdd(&spool[g * HH + jv * 4 + 3], acc[jv].w);
        }
    }
    __syncthreads();
    for (int i = tid; i < NG * HH; i += 128)
        atomicAdd(&g_pooled[i], spool[i]);
}

// ---------------------------------------------------------------------------
// Head MLP; tail-zeroes g_pooled after reading (last consumer).
__global__ void __launch_bounds__(1024) out_kernel(
    const float* __restrict__ ow1, const float* __restrict__ ob1,
    const float* __restrict__ ow2, const float* __restrict__ ob2,
    const float* __restrict__ ow3, const float* __restrict__ ob3,
    const float* __restrict__ ow4, const float* __restrict__ ob4,
    float* __restrict__ out)
{
    __shared__ float sa[NG * HH];
    __shared__ float sbuf[NG * HH];
    int tid = threadIdx.x;
    sa[tid] = g_pooled[tid];
    g_pooled[tid] = 0.f;               // tail-zero for next replay
    __syncthreads();

    int g = tid >> 6, j = tid & 63;

    float v = __ldg(&ob1[j]);
#pragma unroll 16
    for (int k = 0; k < 64; k++) v = fmaf(sa[g * 64 + k], __ldg(&ow1[k * 64 + j]), v);
    sbuf[tid] = fmaxf(v, 0.f);
    __syncthreads();

    v = __ldg(&ob2[j]);
#pragma unroll 16
    for (int k = 0; k < 64; k++) v = fmaf(sbuf[g * 64 + k], __ldg(&ow2[k * 64 + j]), v);
    sa[tid] = fmaxf(v, 0.f);
    __syncthreads();

    v = __ldg(&ob3[j]);
#pragma unroll 16
    for (int k = 0; k < 64; k++) v = fmaf(sa[g * 64 + k], __ldg(&ow3[k * 64 + j]), v);
    sbuf[tid] = fmaxf(v, 0.f);
    __syncthreads();

    if (j < DOUT) {
        float o = __ldg(&ob4[j]);
#pragma unroll 16
        for (int k = 0; k < 64; k++)
            o = fmaf(sbuf[g * 64 + k], __ldg(&ow4[k * DOUT + j]), o);
        out[g * DOUT + j] = o;
    }
}

// ---------------------------------------------------------------------------
extern "C" void kernel_launch(void* const* d_in, const int* in_sizes, int n_in,
                              void* d_out, int out_size) {
    const float* x     = (const float*)d_in[0];
    const int* ei      = (const int*)d_in[1];
    const float* ea    = (const float*)d_in[2];
    const int* batch   = (const int*)d_in[3];
    const float* ew1 = (const float*)d_in[4];
    const float* eb1 = (const float*)d_in[5];
    const float* ew2 = (const float*)d_in[6];
    const float* eb2 = (const float*)d_in[7];
    const float* nw1 = (const float*)d_in[8];
    const float* nb1 = (const float*)d_in[9];
    const float* nw2 = (const float*)d_in[10];
    const float* nb2 = (const float*)d_in[11];
    const float* ow1 = (const float*)d_in[12];
    const float* ob1 = (const float*)d_in[13];
    const float* ow2 = (const float*)d_in[14];
    const float* ob2 = (const float*)d_in[15];
    const float* ow3 = (const float*)d_in[16];
    const float* ob3 = (const float*)d_in[17];
    const float* ow4 = (const float*)d_in[18];
    const float* ob4 = (const float*)d_in[19];
    float* out = (float*)d_out;

    const int node_smem = (4160 + 128 * VPAD + 64 + 1024) * 4;   // 55808 B
    static int smem_set = 0;
    if (!smem_set) {
        cudaFuncSetAttribute(node_fused_kernel,
                             cudaFuncAttributeMaxDynamicSharedMemorySize, node_smem);
        smem_set = 1;
    }

    hist_kernel<<<(NE / 4 + 255) / 256, 256>>>(ei);              // 1
    scan_kernel<<<NB_SCAN, SCAN_T>>>();                          // 2
    fill_kernel<<<(NE + 255) / 256, 256>>>(ei, x, ea);           // 3
    gather_kernel<<<(NN + 7) / 8, 256>>>(x, ew1, eb1);           // 4 <- ncu
    node_fused_kernel<<<(NN + 127) / 128, 128, node_smem>>>(x, batch,
        ew2, eb2, nw1, nb1, nw2, nb2);                           // 5
    out_kernel<<<1, NG * HH>>>(ow1, ob1, ow2, ob2, ow3, ob3, ow4, ob4, out); // 6
}